// round 14
// baseline (speedup 1.0000x reference)
#include <cuda_runtime.h>
#include <math.h>
#include <stdint.h>

// Model constants
constexpr int CD  = 768;
constexpr int CS  = 1024;
constexpr int CB  = 2;
constexpr int CM  = CB * CS;  // 2048
constexpr int CH  = 12;
constexpr int CHD = 64;
constexpr int CL  = 6;
constexpr int CF  = 3072;
constexpr int CV  = 32000;

// Scratch
__device__ float g_x  [CM * CD];
__device__ float g_q  [CM * CD];
__device__ float g_k  [CM * CD];
__device__ float g_v  [CM * CD];
__device__ float g_att[CM * CD];
__device__ float g_ff [CM * CF];

// Single extern shared symbol, cast per-kernel
extern __shared__ char s_raw[];

// ---------------------------------------------------------------------------
// Helpers
// ---------------------------------------------------------------------------
__device__ __forceinline__ uint32_t f2tf(float f) {
    uint32_t u;
    asm("cvt.rna.tf32.f32 %0, %1;" : "=r"(u) : "f"(f));
    return u;
}
__device__ __forceinline__ void mma_tf32(float* c, const uint32_t* a, const uint32_t* b) {
    asm volatile(
        "mma.sync.aligned.m16n8k8.row.col.f32.tf32.tf32.f32 "
        "{%0,%1,%2,%3}, {%4,%5,%6,%7}, {%8,%9}, {%0,%1,%2,%3};"
        : "+f"(c[0]), "+f"(c[1]), "+f"(c[2]), "+f"(c[3])
        : "r"(a[0]), "r"(a[1]), "r"(a[2]), "r"(a[3]), "r"(b[0]), "r"(b[1]));
}
#define CP_ASYNC16(dst, src) \
    asm volatile("cp.async.ca.shared.global [%0], [%1], 16;" :: "r"(dst), "l"(src))
#define CP_COMMIT() asm volatile("cp.async.commit_group;")
#define CP_WAIT1()  asm volatile("cp.async.wait_group 1;")

// ---------------------------------------------------------------------------
// Embedding
// ---------------------------------------------------------------------------
__global__ void embed_kernel(const int* __restrict__ ids, const float* __restrict__ emb,
                             const float* __restrict__ pe, float* __restrict__ out) {
    int idx = blockIdx.x * blockDim.x + threadIdx.x;
    if (idx >= CM * CD) return;
    int r = idx / CD;
    int d = idx - r * CD;
    int s = r & (CS - 1);
    out[idx] = emb[ids[r] * CD + d] * 27.712812921102035f + pe[s * CD + d];
}

// ---------------------------------------------------------------------------
// tf32 mma.sync GEMM core v4: C[M,N] = A[M,K] @ B[K,N] + bias (ACT=1: GELU)
// BM x 128 CTA tile, BK=32, THREE smem stages + cp.async wait_group 1 so the
// newest B-load group stays in flight through a full chunk of compute.
// B raw fp32 via cp.async, tf32 cvt at fragment load (prefetched one k-slice
// ahead). A: LDG->cvt->STS, layout [m][BK+4]. B: [k][n ^ ((k&3)<<3)].
// ---------------------------------------------------------------------------
template <int ACT, int BM, int BK>
__device__ __forceinline__ void gemm_core(const float* __restrict__ A,
                                          const float* __restrict__ B,
                                          const float* __restrict__ bias,
                                          float* __restrict__ C,
                                          int N, int K, int r0, int c0,
                                          uint32_t* sm) {
    constexpr int AW  = BK + 4;          // k-words + pad
    constexpr int SA  = BM * AW;         // A stage words
    constexpr int SB  = BK * 128;        // B stage words
    constexpr int ABo = 3 * SA;          // B region word offset (3 stages)
    constexpr int AIT = BM * BK / 1024;  // A float4 per thread per stage
    constexpr int BIT = BK / 8;          // B float4 per thread per stage
    constexpr int MT  = BM / 32;         // 16-row m-tiles per warp
    constexpr int KS  = BK / 8;          // k-slices per chunk
    constexpr int AQ  = BK / 4;          // A float4 per row

    const int tid  = threadIdx.x;
    const int lane = tid & 31;
    const int wid  = tid >> 5;
    const int wr   = wid >> 2;
    const int wc   = wid & 3;
    const int lr   = lane >> 2;
    const int lc   = lane & 3;
    const int NK   = K / BK;

    const float* Ag = A + (size_t)r0 * K;
    const float* Bg = B + c0;
    const uint32_t smb = (uint32_t)__cvta_generic_to_shared(sm);

    float cc[MT][4][4];
#pragma unroll
    for (int mt = 0; mt < MT; mt++)
#pragma unroll
        for (int nt = 0; nt < 4; nt++)
#pragma unroll
            for (int j = 0; j < 4; j++) cc[mt][nt][j] = 0.0f;

    // A staging coords
    int am[AIT], ak[AIT];
#pragma unroll
    for (int it = 0; it < AIT; it++) {
        int i = tid + it * 256;
        am[it] = i / AQ;
        ak[it] = (i % AQ) << 2;
    }
    // B staging coords
    int bk[BIT], bn[BIT];
#pragma unroll
    for (int it = 0; it < BIT; it++) {
        int i = tid + it * 256;
        bk[it] = i >> 5;
        bn[it] = (i & 31) << 2;
    }

    float4 rA[AIT];

    // ---- prologue: chunks 0,1 staged; chunk 2 in registers ----
#pragma unroll
    for (int it = 0; it < AIT; it++)
        rA[it] = *(const float4*)(Ag + (size_t)am[it] * K + ak[it]);
#pragma unroll
    for (int it = 0; it < BIT; it++) {
        uint32_t dst = smb + 4u * (ABo + bk[it] * 128 + (bn[it] ^ ((bk[it] & 3) << 3)));
        CP_ASYNC16(dst, Bg + (size_t)bk[it] * N + bn[it]);
    }
    CP_COMMIT();
#pragma unroll
    for (int it = 0; it < AIT; it++) {
        uint4 v;
        v.x = f2tf(rA[it].x);
        v.y = f2tf(rA[it].y);
        v.z = f2tf(rA[it].z);
        v.w = f2tf(rA[it].w);
        *(uint4*)&sm[am[it] * AW + ak[it]] = v;
    }
    if (NK > 1) {
#pragma unroll
        for (int it = 0; it < AIT; it++)
            rA[it] = *(const float4*)(Ag + (size_t)am[it] * K + BK + ak[it]);
#pragma unroll
        for (int it = 0; it < BIT; it++) {
            uint32_t dst = smb + 4u * (ABo + SB + bk[it] * 128 +
                                       (bn[it] ^ ((bk[it] & 3) << 3)));
            CP_ASYNC16(dst, Bg + (size_t)(BK + bk[it]) * N + bn[it]);
        }
    }
    CP_COMMIT();
    if (NK > 1) {
        uint32_t* As1 = sm + SA;
#pragma unroll
        for (int it = 0; it < AIT; it++) {
            uint4 v;
            v.x = f2tf(rA[it].x);
            v.y = f2tf(rA[it].y);
            v.z = f2tf(rA[it].z);
            v.w = f2tf(rA[it].w);
            *(uint4*)&As1[am[it] * AW + ak[it]] = v;
        }
    }
    if (NK > 2) {
#pragma unroll
        for (int it = 0; it < AIT; it++)
            rA[it] = *(const float4*)(Ag + (size_t)am[it] * K + 2 * BK + ak[it]);
    }

    const int xb = lc << 3;  // B swizzle: (k0&3)<<3 == lc<<3 for k0 = ks*8+lc

    // ---- main loop ----
#pragma unroll 1
    for (int j = 0; j < NK; j++) {
        const int s = j % 3;
        CP_WAIT1();               // B(j) done; B(j+1) may stay in flight
        __syncthreads();

        if (j + 2 < NK) {
            const int s2 = (j + 2) % 3;
#pragma unroll
            for (int it = 0; it < BIT; it++) {
                uint32_t dst = smb + 4u * (ABo + s2 * SB + bk[it] * 128 +
                                           (bn[it] ^ ((bk[it] & 3) << 3)));
                CP_ASYNC16(dst, Bg + (size_t)((j + 2) * BK + bk[it]) * N + bn[it]);
            }
        }
        CP_COMMIT();

        if (j + 2 < NK) {
            uint32_t* As2 = sm + ((j + 2) % 3) * SA;
#pragma unroll
            for (int it = 0; it < AIT; it++) {
                uint4 v;
                v.x = f2tf(rA[it].x);
                v.y = f2tf(rA[it].y);
                v.z = f2tf(rA[it].z);
                v.w = f2tf(rA[it].w);
                *(uint4*)&As2[am[it] * AW + ak[it]] = v;
            }
            if (j + 3 < NK) {
#pragma unroll
                for (int it = 0; it < AIT; it++)
                    rA[it] = *(const float4*)(Ag + (size_t)am[it] * K + (j + 3) * BK + ak[it]);
            }
        }

        const uint32_t* As_ = sm + s * SA;
        const uint32_t* Bs_ = sm + ABo + s * SB;

        // B-fragment prefetch pipeline over KS k-slices
        uint32_t bf[2][4][2];
        {
            const int k0 = lc;
#pragma unroll
            for (int nt = 0; nt < 4; nt++) {
                int n = wc * 32 + nt * 8 + lr;
                bf[0][nt][0] = f2tf(__uint_as_float(Bs_[k0 * 128 + (n ^ xb)]));
                bf[0][nt][1] = f2tf(__uint_as_float(Bs_[(k0 + 4) * 128 + (n ^ xb)]));
            }
        }
#pragma unroll
        for (int ks = 0; ks < KS; ks++) {
            if (ks < KS - 1) {
                const int k0 = (ks + 1) * 8 + lc;
#pragma unroll
                for (int nt = 0; nt < 4; nt++) {
                    int n = wc * 32 + nt * 8 + lr;
                    bf[(ks + 1) & 1][nt][0] = f2tf(__uint_as_float(Bs_[k0 * 128 + (n ^ xb)]));
                    bf[(ks + 1) & 1][nt][1] = f2tf(__uint_as_float(Bs_[(k0 + 4) * 128 + (n ^ xb)]));
                }
            }
            const int k0 = ks * 8 + lc;
            uint32_t af[MT][4];
#pragma unroll
            for (int mt = 0; mt < MT; mt++) {
                int m = wr * (BM / 2) + mt * 16 + lr;
                af[mt][0] = As_[m * AW + k0];
                af[mt][1] = As_[(m + 8) * AW + k0];
                af[mt][2] = As_[m * AW + k0 + 4];
                af[mt][3] = As_[(m + 8) * AW + k0 + 4];
            }
#pragma unroll
            for (int mt = 0; mt < MT; mt++)
#pragma unroll
                for (int nt = 0; nt < 4; nt++) mma_tf32(cc[mt][nt], af[mt], bf[ks & 1][nt]);
        }
    }

    // ---- epilogue ----
#pragma unroll
    for (int nt = 0; nt < 4; nt++) {
        int col = c0 + wc * 32 + nt * 8 + 2 * lc;
        float b0 = bias[col], b1 = bias[col + 1];
#pragma unroll
        for (int mt = 0; mt < MT; mt++) {
            int rlo = r0 + wr * (BM / 2) + mt * 16 + lr;
            float o0 = cc[mt][nt][0] + b0;
            float o1 = cc[mt][nt][1] + b1;
            float o2 = cc[mt][nt][2] + b0;
            float o3 = cc[mt][nt][3] + b1;
            if (ACT == 1) {
                o0 = 0.5f * o0 * (1.0f + erff(o0 * 0.70710678118654752f));
                o1 = 0.5f * o1 * (1.0f + erff(o1 * 0.70710678118654752f));
                o2 = 0.5f * o2 * (1.0f + erff(o2 * 0.70710678118654752f));
                o3 = 0.5f * o3 * (1.0f + erff(o3 * 0.70710678118654752f));
            }
            *(float2*)&C[(size_t)rlo * N + col]       = make_float2(o0, o1);
            *(float2*)&C[(size_t)(rlo + 8) * N + col] = make_float2(o2, o3);
        }
    }
}

template <int ACT, int BM, int BK>
__global__ void __launch_bounds__(256, 2) gemm_mma(const float* __restrict__ A,
                                                   const float* __restrict__ B,
                                                   const float* __restrict__ bias,
                                                   float* __restrict__ C, int N, int K) {
    gemm_core<ACT, BM, BK>(A, B, bias, C, N, K, blockIdx.x * BM, blockIdx.y * 128,
                           (uint32_t*)s_raw);
}

__global__ void __launch_bounds__(256, 2) gemm_qkv(const float* __restrict__ A,
                                                   const float* __restrict__ Bq,
                                                   const float* __restrict__ Bk,
                                                   const float* __restrict__ Bv,
                                                   const float* __restrict__ bq,
                                                   const float* __restrict__ bk,
                                                   const float* __restrict__ bv,
                                                   float* __restrict__ Cq,
                                                   float* __restrict__ Ck,
                                                   float* __restrict__ Cv) {
    const float* B;
    const float* bi;
    float* C;
    if (blockIdx.z == 0)      { B = Bq; bi = bq; C = Cq; }
    else if (blockIdx.z == 1) { B = Bk; bi = bk; C = Ck; }
    else                      { B = Bv; bi = bv; C = Cv; }
    gemm_core<0, 128, 32>(A, B, bi, C, CD, CD, blockIdx.x * 128, blockIdx.y * 128,
                          (uint32_t*)s_raw);
}

// ---------------------------------------------------------------------------
// Tensor-core causal flash attention (tf32 mma.sync) — R11 version, occ 1
// ---------------------------------------------------------------------------
__global__ void __launch_bounds__(256, 1) attn_mma(const float* __restrict__ q,
                                                   const float* __restrict__ k,
                                                   const float* __restrict__ v,
                                                   float* __restrict__ o) {
    float* sm = (float*)s_raw;
    constexpr int QW = 68, PWD = 76, KW = 68, VW = 72;
    constexpr int OFF_K = 9728;
    constexpr int KSTG  = 64 * KW;
    constexpr int OFF_V = OFF_K + 2 * KSTG;
    constexpr int VSTG  = 64 * VW;

    const int tid = threadIdx.x, lane = tid & 31, wid = tid >> 5;
    const int g = lane >> 2, t = lane & 3;
    const int qt = (int)(gridDim.x - 1 - blockIdx.x);
    const int h = blockIdx.y, b = blockIdx.z;
    const int qbase = qt * 128;
    const int rowoff = b * CS;
    const int hd = h * CHD;
    const int nkt = 2 * qt + 2;
    const uint32_t smb = (uint32_t)__cvta_generic_to_shared(sm);

#pragma unroll
    for (int it = 0; it < 8; it++) {
        int i = tid + it * 256;
        int r = i >> 4, c = (i & 15) << 2;
        float4 qv = *(const float4*)(q + (size_t)(rowoff + qbase + r) * CD + hd + c);
        qv.x *= 0.125f; qv.y *= 0.125f; qv.z *= 0.125f; qv.w *= 0.125f;
        *(float4*)(sm + r * QW + c) = qv;
    }
#pragma unroll
    for (int j = 0; j < 4; j++) {
        int i = tid + j * 256;
        int r = i >> 4, c = (i & 15) << 2;
        CP_ASYNC16(smb + 4u * (OFF_K + r * KW + c),
                   k + (size_t)(rowoff + r) * CD + hd + c);
        CP_ASYNC16(smb + 4u * (OFF_V + r * VW + c),
                   v + (size_t)(rowoff + r) * CD + hd + c);
    }
    CP_COMMIT();
    __syncthreads();

    uint32_t qf[8][4];
    {
        int r0 = wid * 16 + g;
#pragma unroll
        for (int kk = 0; kk < 8; kk++) {
            qf[kk][0] = f2tf(sm[r0 * QW + kk * 8 + t]);
            qf[kk][1] = f2tf(sm[(r0 + 8) * QW + kk * 8 + t]);
            qf[kk][2] = f2tf(sm[r0 * QW + kk * 8 + t + 4]);
            qf[kk][3] = f2tf(sm[(r0 + 8) * QW + kk * 8 + t + 4]);
        }
    }

    float m0 = -1e30f, m1 = -1e30f, l0 = 0.0f, l1 = 0.0f;
    float o_[8][4];
#pragma unroll
    for (int nt = 0; nt < 8; nt++)
#pragma unroll
        for (int j = 0; j < 4; j++) o_[nt][j] = 0.0f;

    const int wrow = qbase + wid * 16;

#pragma unroll 1
    for (int kt = 0; kt < nkt; kt++) {
        const int s = kt & 1;
        __syncthreads();
        if (kt + 1 < nkt) {
#pragma unroll
            for (int j = 0; j < 4; j++) {
                int i = tid + j * 256;
                int r = i >> 4, c = (i & 15) << 2;
                CP_ASYNC16(smb + 4u * (OFF_K + (s ^ 1) * KSTG + r * KW + c),
                           k + (size_t)(rowoff + (kt + 1) * 64 + r) * CD + hd + c);
                CP_ASYNC16(smb + 4u * (OFF_V + (s ^ 1) * VSTG + r * VW + c),
                           v + (size_t)(rowoff + (kt + 1) * 64 + r) * CD + hd + c);
            }
        }
        CP_COMMIT();
        CP_WAIT1();
        __syncthreads();

        if (kt * 64 > wrow + 15) continue;

        const float* Ks = sm + OFF_K + s * KSTG;
        const float* Vs = sm + OFF_V + s * VSTG;

        float c_[8][4];
#pragma unroll
        for (int nt = 0; nt < 8; nt++)
#pragma unroll
            for (int j = 0; j < 4; j++) c_[nt][j] = 0.0f;
#pragma unroll
        for (int kk = 0; kk < 8; kk++) {
#pragma unroll
            for (int nt = 0; nt < 8; nt++) {
                uint32_t bf[2];
                bf[0] = f2tf(Ks[(nt * 8 + g) * KW + kk * 8 + t]);
                bf[1] = f2tf(Ks[(nt * 8 + g) * KW + kk * 8 + t + 4]);
                mma_tf32(c_[nt], qf[kk], bf);
            }
        }

        if (kt * 64 + 63 > wrow) {
            int r0g = wrow + g, r1g = r0g + 8;
#pragma unroll
            for (int nt = 0; nt < 8; nt++) {
                int col = kt * 64 + nt * 8 + 2 * t;
                if (col     > r0g) c_[nt][0] = -1e9f;
                if (col + 1 > r0g) c_[nt][1] = -1e9f;
                if (col     > r1g) c_[nt][2] = -1e9f;
                if (col + 1 > r1g) c_[nt][3] = -1e9f;
            }
        }

        float tm0 = c_[0][0], tm1 = c_[0][2];
#pragma unroll
        for (int nt = 0; nt < 8; nt++) {
            tm0 = fmaxf(tm0, fmaxf(c_[nt][0], c_[nt][1]));
            tm1 = fmaxf(tm1, fmaxf(c_[nt][2], c_[nt][3]));
        }
        tm0 = fmaxf(tm0, __shfl_xor_sync(0xffffffffu, tm0, 1));
        tm0 = fmaxf(tm0, __shfl_xor_sync(0xffffffffu, tm0, 2));
        tm1 = fmaxf(tm1, __shfl_xor_sync(0xffffffffu, tm1, 1));
        tm1 = fmaxf(tm1, __shfl_xor_sync(0xffffffffu, tm1, 2));

        float mn0 = fmaxf(m0, tm0), mn1 = fmaxf(m1, tm1);
        float al0 = __expf(m0 - mn0), al1 = __expf(m1 - mn1);
        float ls0 = 0.0f, ls1 = 0.0f;
#pragma unroll
        for (int nt = 0; nt < 8; nt++) {
            c_[nt][0] = __expf(c_[nt][0] - mn0);
            c_[nt][1] = __expf(c_[nt][1] - mn0);
            c_[nt][2] = __expf(c_[nt][2] - mn1);
            c_[nt][3] = __expf(c_[nt][3] - mn1);
            ls0 += c_[nt][0] + c_[nt][1];
            ls1 += c_[nt][2] + c_[nt][3];
        }
        ls0 += __shfl_xor_sync(0xffffffffu, ls0, 1);
        ls0 += __shfl_xor_sync(0xffffffffu, ls0, 2);
        ls1 += __shfl_xor_sync(0xffffffffu, ls1, 1);
        ls1 += __shfl_xor_sync(0xffffffffu, ls1, 2);
        l0 = l0 * al0 + ls0; m0 = mn0;
        l1 = l1 * al1 + ls1; m1 = mn1;
#pragma unroll
        for (int nt = 0; nt < 8; nt++) {
            o_[nt][0] *= al0; o_[nt][1] *= al0;
            o_[nt][2] *= al1; o_[nt][3] *= al1;
        }

        float* Pw = sm + wid * 16 * PWD;
#pragma unroll
        for (int nt = 0; nt < 8; nt++) {
            int cc0 = nt * 8 + 2 * t;
            Pw[g * PWD + cc0]           = __uint_as_float(f2tf(c_[nt][0]));
            Pw[g * PWD + cc0 + 1]       = __uint_as_float(f2tf(c_[nt][1]));
            Pw[(g + 8) * PWD + cc0]     = __uint_as_float(f2tf(c_[nt][2]));
            Pw[(g + 8) * PWD + cc0 + 1] = __uint_as_float(f2tf(c_[nt][3]));
        }
        __syncwarp();

#pragma unroll
        for (int kk = 0; kk < 8; kk++) {
            uint32_t af[4];
            af[0] = __float_as_uint(Pw[g * PWD + kk * 8 + t]);
            af[1] = __float_as_uint(Pw[(g + 8) * PWD + kk * 8 + t]);
            af[2] = __float_as_uint(Pw[g * PWD + kk * 8 + t + 4]);
            af[3] = __float_as_uint(Pw[(g + 8) * PWD + kk * 8 + t + 4]);
#pragma unroll
            for (int nt = 0; nt < 8; nt++) {
                uint32_t bf[2];
                bf[0] = f2tf(Vs[(kk * 8 + t) * VW + nt * 8 + g]);
                bf[1] = f2tf(Vs[(kk * 8 + t + 4) * VW + nt * 8 + g]);
                mma_tf32(o_[nt], af, bf);
            }
        }
        __syncwarp();
    }

    float i0 = 1.0f / l0, i1 = 1.0f / l1;
    int row0 = rowoff + qbase + wid * 16 + g;
#pragma unroll
    for (int nt = 0; nt < 8; nt++) {
        int col = hd + nt * 8 + 2 * t;
        *(float2*)&o[(size_t)row0 * CD + col] = make_float2(o_[nt][0] * i0, o_[nt][1] * i0);
        *(float2*)&o[(size_t)(row0 + 8) * CD + col] = make_float2(o_[nt][2] * i1, o_[nt][3] * i1);
    }
}

// ---------------------------------------------------------------------------
// LayerNorm
// ---------------------------------------------------------------------------
__global__ void ln_kernel(const float* __restrict__ x, const float* __restrict__ res,
                          const float* __restrict__ g, const float* __restrict__ b,
                          float* __restrict__ out) {
    int r = blockIdx.x, t = threadIdx.x;
    __shared__ float red[8];
    int base = r * CD;
    float a0 = x[base + t], a1 = x[base + t + 256], a2 = x[base + t + 512];
    if (res) {
        a0 += res[base + t];
        a1 += res[base + t + 256];
        a2 += res[base + t + 512];
    }
    float sm = a0 + a1 + a2;
#pragma unroll
    for (int o = 16; o; o >>= 1) sm += __shfl_xor_sync(0xffffffffu, sm, o);
    if ((t & 31) == 0) red[t >> 5] = sm;
    __syncthreads();
    float mean = (red[0] + red[1] + red[2] + red[3] + red[4] + red[5] + red[6] + red[7]) *
                 (1.0f / CD);
    __syncthreads();
    float d0 = a0 - mean, d1 = a1 - mean, d2 = a2 - mean;
    float vs = d0 * d0 + d1 * d1 + d2 * d2;
#pragma unroll
    for (int o = 16; o; o >>= 1) vs += __shfl_xor_sync(0xffffffffu, vs, o);
    if ((t & 31) == 0) red[t >> 5] = vs;
    __syncthreads();
    float var = (red[0] + red[1] + red[2] + red[3] + red[4] + red[5] + red[6] + red[7]) *
                (1.0f / CD);
    float rstd = rsqrtf(var + 1e-5f);
    out[base + t]       = d0 * rstd * g[t]       + b[t];
    out[base + t + 256] = d1 * rstd * g[t + 256] + b[t + 256];
    out[base + t + 512] = d2 * rstd * g[t + 512] + b[t + 512];
}

// ---------------------------------------------------------------------------
// Launch
// ---------------------------------------------------------------------------
extern "C" void kernel_launch(void* const* d_in, const int* in_sizes, int n_in,
                              void* d_out, int out_size) {
    const int*   ids   = (const int*)  d_in[0];
    const float* emb   = (const float*)d_in[1];
    const float* pe    = (const float*)d_in[2];
    const float* wq    = (const float*)d_in[3];
    const float* bq    = (const float*)d_in[4];
    const float* wk    = (const float*)d_in[5];
    const float* bk    = (const float*)d_in[6];
    const float* wv    = (const float*)d_in[7];
    const float* bv    = (const float*)d_in[8];
    const float* wo    = (const float*)d_in[9];
    const float* bo    = (const float*)d_in[10];
    const float* ln1g  = (const float*)d_in[11];
    const float* ln1b  = (const float*)d_in[12];
    const float* w1    = (const float*)d_in[13];
    const float* b1    = (const float*)d_in[14];
    const float* w2    = (const float*)d_in[15];
    const float* b2    = (const float*)d_in[16];
    const float* ln2g  = (const float*)d_in[17];
    const float* ln2b  = (const float*)d_in[18];
    const float* lnfg  = (const float*)d_in[19];
    const float* lnfb  = (const float*)d_in[20];
    const float* headw = (const float*)d_in[21];
    const float* headb = (const float*)d_in[22];
    float* out = (float*)d_out;

    float *x, *q, *k, *v, *att, *ff;
    cudaGetSymbolAddress((void**)&x,   g_x);
    cudaGetSymbolAddress((void**)&q,   g_q);
    cudaGetSymbolAddress((void**)&k,   g_k);
    cudaGetSymbolAddress((void**)&v,   g_v);
    cudaGetSymbolAddress((void**)&att, g_att);
    cudaGetSymbolAddress((void**)&ff,  g_ff);

    const int SMEM_ATTN  = (9728 + 2 * 4352 + 2 * 4608) * 4;      // 110592
    const int SMEM_G128  = (3 * 128 * 36 + 3 * 32 * 128) * 4;     // 104448 (BK=32)
    const int SMEM_G64   = (3 * 64 * 36 + 3 * 32 * 128) * 4;      // 76800  (BK=32)
    cudaFuncSetAttribute(attn_mma, cudaFuncAttributeMaxDynamicSharedMemorySize, SMEM_ATTN);
    cudaFuncSetAttribute(gemm_mma<0, 128, 32>, cudaFuncAttributeMaxDynamicSharedMemorySize, SMEM_G128);
    cudaFuncSetAttribute(gemm_mma<1, 128, 32>, cudaFuncAttributeMaxDynamicSharedMemorySize, SMEM_G128);
    cudaFuncSetAttribute(gemm_mma<0, 64, 32>,  cudaFuncAttributeMaxDynamicSharedMemorySize, SMEM_G64);
    cudaFuncSetAttribute(gemm_qkv, cudaFuncAttributeMaxDynamicSharedMemorySize, SMEM_G128);

    embed_kernel<<<(CM * CD + 255) / 256, 256>>>(ids, emb, pe, x);

    dim3 gQKV(CM / 128, CD / 128, 3);   // 288
    dim3 gP64(CM / 64,  CD / 128);      // 192
    dim3 gF1 (CM / 128, CF / 128);      // 384
    dim3 gH  (CM / 128, CV / 128);      // 4000
    dim3 gATT(CS / 128, CH, CB);        // 192

    for (int l = 0; l < CL; l++) {
        size_t wOff = (size_t)l * CD * CD;
        gemm_qkv<<<gQKV, 256, SMEM_G128>>>(x, wq + wOff, wk + wOff, wv + wOff,
                                           bq + l * CD, bk + l * CD, bv + l * CD, q, k, v);
        attn_mma<<<gATT, 256, SMEM_ATTN>>>(q, k, v, att);
        gemm_mma<0, 64, 32><<<gP64, 256, SMEM_G64>>>(att, wo + wOff, bo + l * CD, q, CD, CD);
        ln_kernel<<<CM, 256>>>(x, q, ln1g + l * CD, ln1b + l * CD, x);
        gemm_mma<1, 128, 32><<<gF1, 256, SMEM_G128>>>(x, w1 + (size_t)l * CD * CF,
                                                      b1 + l * CF, ff, CF, CD);
        gemm_mma<0, 64, 32><<<gP64, 256, SMEM_G64>>>(ff, w2 + (size_t)l * CF * CD,
                                                     b2 + l * CD, q, CD, CF);
        ln_kernel<<<CM, 256>>>(x, q, ln2g + l * CD, ln2b + l * CD, x);
    }

    ln_kernel<<<CM, 256>>>(x, nullptr, lnfg, lnfb, q);
    gemm_mma<0, 128, 32><<<gH, 256, SMEM_G128>>>(q, headw, headb, out, CV, CD);
}

// round 15
// speedup vs baseline: 1.8741x; 1.8741x over previous
#include <cuda_runtime.h>
#include <math.h>
#include <stdint.h>

// Model constants
constexpr int CD  = 768;
constexpr int CS  = 1024;
constexpr int CB  = 2;
constexpr int CM  = CB * CS;  // 2048
constexpr int CH  = 12;
constexpr int CHD = 64;
constexpr int CL  = 6;
constexpr int CF  = 3072;
constexpr int CV  = 32000;

// Scratch
__device__ float g_x  [CM * CD];
__device__ float g_q  [CM * CD];
__device__ float g_k  [CM * CD];
__device__ float g_v  [CM * CD];
__device__ float g_att[CM * CD];
__device__ float g_ff [CM * CF];

// Single extern shared symbol, cast per-kernel
extern __shared__ char s_raw[];

// ---------------------------------------------------------------------------
// Helpers
// ---------------------------------------------------------------------------
__device__ __forceinline__ uint32_t f2tf(float f) {
    uint32_t u;
    asm("cvt.rna.tf32.f32 %0, %1;" : "=r"(u) : "f"(f));
    return u;
}
__device__ __forceinline__ void mma_tf32(float* c, const uint32_t* a, const uint32_t* b) {
    asm volatile(
        "mma.sync.aligned.m16n8k8.row.col.f32.tf32.tf32.f32 "
        "{%0,%1,%2,%3}, {%4,%5,%6,%7}, {%8,%9}, {%0,%1,%2,%3};"
        : "+f"(c[0]), "+f"(c[1]), "+f"(c[2]), "+f"(c[3])
        : "r"(a[0]), "r"(a[1]), "r"(a[2]), "r"(a[3]), "r"(b[0]), "r"(b[1]));
}
#define CP_ASYNC16(dst, src) \
    asm volatile("cp.async.ca.shared.global [%0], [%1], 16;" :: "r"(dst), "l"(src))
#define CP_COMMIT() asm volatile("cp.async.commit_group;")
#define CP_WAIT0()  asm volatile("cp.async.wait_group 0;")
#define CP_WAIT1()  asm volatile("cp.async.wait_group 1;")

// ---------------------------------------------------------------------------
// Embedding
// ---------------------------------------------------------------------------
__global__ void embed_kernel(const int* __restrict__ ids, const float* __restrict__ emb,
                             const float* __restrict__ pe, float* __restrict__ out) {
    int idx = blockIdx.x * blockDim.x + threadIdx.x;
    if (idx >= CM * CD) return;
    int r = idx / CD;
    int d = idx - r * CD;
    int s = r & (CS - 1);
    out[idx] = emb[ids[r] * CD + d] * 27.712812921102035f + pe[s * CD + d];
}

// ---------------------------------------------------------------------------
// tf32 mma.sync GEMM core (R11 configuration): C = A @ B + bias (ACT=1: GELU)
// BM x 128 CTA tile, BK=32, 2-stage pipeline, one sync per 32 k.
// B raw fp32 via cp.async, tf32 cvt at fragment load (prefetched one k-slice
// ahead). A: LDG->cvt->STS, layout [m][36]. B: [k][n ^ ((k&3)<<3)].
// ---------------------------------------------------------------------------
template <int ACT, int BM>
__device__ __forceinline__ void gemm_core(const float* __restrict__ A,
                                          const float* __restrict__ B,
                                          const float* __restrict__ bias,
                                          float* __restrict__ C,
                                          int N, int K, int r0, int c0,
                                          uint32_t* sm) {
    constexpr int AW  = 36;          // 32 k-words + 4 pad
    constexpr int SA  = BM * AW;     // A stage words
    constexpr int SB  = 32 * 128;    // B stage words (4096)
    constexpr int ABo = 2 * SA;      // B region word offset
    constexpr int AIT = BM / 32;     // A float4 per thread per stage
    constexpr int MT  = BM / 32;     // 16-row m-tiles per warp

    const int tid  = threadIdx.x;
    const int lane = tid & 31;
    const int wid  = tid >> 5;
    const int wr   = wid >> 2;
    const int wc   = wid & 3;
    const int lr   = lane >> 2;
    const int lc   = lane & 3;
    const int NK   = K >> 5;

    const float* Ag = A + (size_t)r0 * K;
    const float* Bg = B + c0;
    const uint32_t smb = (uint32_t)__cvta_generic_to_shared(sm);

    float cc[MT][4][4];
#pragma unroll
    for (int mt = 0; mt < MT; mt++)
#pragma unroll
        for (int nt = 0; nt < 4; nt++)
#pragma unroll
            for (int j = 0; j < 4; j++) cc[mt][nt][j] = 0.0f;

    // A staging coords: idx = tid + it*256 -> row = idx>>3, k4 = (idx&7)*4
    int am[AIT], ak[AIT];
#pragma unroll
    for (int it = 0; it < AIT; it++) {
        int i = tid + it * 256;
        am[it] = i >> 3;
        ak[it] = (i & 7) << 2;
    }
    // B staging coords: idx = tid + it*256 (it<4) -> k = idx>>5, n4 = (idx&31)*4
    int bk[4], bn[4];
#pragma unroll
    for (int it = 0; it < 4; it++) {
        int i = tid + it * 256;
        bk[it] = i >> 5;
        bn[it] = (i & 31) << 2;
    }

    float4 rA[AIT];

    // ---- prologue: chunk 0 ----
#pragma unroll
    for (int it = 0; it < AIT; it++)
        rA[it] = *(const float4*)(Ag + (size_t)am[it] * K + ak[it]);
#pragma unroll
    for (int it = 0; it < 4; it++) {
        uint32_t dst = smb + 4u * (ABo + bk[it] * 128 + (bn[it] ^ ((bk[it] & 3) << 3)));
        CP_ASYNC16(dst, Bg + (size_t)bk[it] * N + bn[it]);
    }
    CP_COMMIT();
#pragma unroll
    for (int it = 0; it < AIT; it++) {
        uint4 v;
        v.x = f2tf(rA[it].x);
        v.y = f2tf(rA[it].y);
        v.z = f2tf(rA[it].z);
        v.w = f2tf(rA[it].w);
        *(uint4*)&sm[am[it] * AW + ak[it]] = v;
    }
    // LDG A chunk 1
    if (NK > 1) {
#pragma unroll
        for (int it = 0; it < AIT; it++)
            rA[it] = *(const float4*)(Ag + (size_t)am[it] * K + 32 + ak[it]);
    }

    const int xb = lc << 3;  // B swizzle term: (k0&3)<<3 == lc<<3 for k0 = ks*8+lc

    // ---- main loop ----
#pragma unroll 1
    for (int j = 0; j < NK; j++) {
        const int s = j & 1;
        CP_WAIT0();
        __syncthreads();

        if (j + 1 < NK) {
            const int s1 = s ^ 1;
            // B(j+1) -> stage s1
#pragma unroll
            for (int it = 0; it < 4; it++) {
                uint32_t dst = smb + 4u * (ABo + s1 * SB + bk[it] * 128 +
                                           (bn[it] ^ ((bk[it] & 3) << 3)));
                CP_ASYNC16(dst, Bg + (size_t)((j + 1) * 32 + bk[it]) * N + bn[it]);
            }
            // A(j+1): STS from rA
            uint32_t* As1 = sm + s1 * SA;
#pragma unroll
            for (int it = 0; it < AIT; it++) {
                uint4 v;
                v.x = f2tf(rA[it].x);
                v.y = f2tf(rA[it].y);
                v.z = f2tf(rA[it].z);
                v.w = f2tf(rA[it].w);
                *(uint4*)&As1[am[it] * AW + ak[it]] = v;
            }
            // LDG A(j+2)
            if (j + 2 < NK) {
#pragma unroll
                for (int it = 0; it < AIT; it++)
                    rA[it] = *(const float4*)(Ag + (size_t)am[it] * K + (j + 2) * 32 + ak[it]);
            }
        }
        CP_COMMIT();

        const uint32_t* As_ = sm + s * SA;
        const uint32_t* Bs_ = sm + ABo + s * SB;

        // B-fragment prefetch pipeline over 4 k-slices
        uint32_t bf[2][4][2];
        {
            const int k0 = lc;
#pragma unroll
            for (int nt = 0; nt < 4; nt++) {
                int n = wc * 32 + nt * 8 + lr;
                bf[0][nt][0] = f2tf(__uint_as_float(Bs_[k0 * 128 + (n ^ xb)]));
                bf[0][nt][1] = f2tf(__uint_as_float(Bs_[(k0 + 4) * 128 + (n ^ xb)]));
            }
        }
#pragma unroll
        for (int ks = 0; ks < 4; ks++) {
            if (ks < 3) {
                const int k0 = (ks + 1) * 8 + lc;
#pragma unroll
                for (int nt = 0; nt < 4; nt++) {
                    int n = wc * 32 + nt * 8 + lr;
                    bf[(ks + 1) & 1][nt][0] = f2tf(__uint_as_float(Bs_[k0 * 128 + (n ^ xb)]));
                    bf[(ks + 1) & 1][nt][1] = f2tf(__uint_as_float(Bs_[(k0 + 4) * 128 + (n ^ xb)]));
                }
            }
            const int k0 = ks * 8 + lc;
            uint32_t af[MT][4];
#pragma unroll
            for (int mt = 0; mt < MT; mt++) {
                int m = wr * (BM / 2) + mt * 16 + lr;
                af[mt][0] = As_[m * AW + k0];
                af[mt][1] = As_[(m + 8) * AW + k0];
                af[mt][2] = As_[m * AW + k0 + 4];
                af[mt][3] = As_[(m + 8) * AW + k0 + 4];
            }
#pragma unroll
            for (int mt = 0; mt < MT; mt++)
#pragma unroll
                for (int nt = 0; nt < 4; nt++) mma_tf32(cc[mt][nt], af[mt], bf[ks & 1][nt]);
        }
    }

    // ---- epilogue ----
#pragma unroll
    for (int nt = 0; nt < 4; nt++) {
        int col = c0 + wc * 32 + nt * 8 + 2 * lc;
        float b0 = bias[col], b1 = bias[col + 1];
#pragma unroll
        for (int mt = 0; mt < MT; mt++) {
            int rlo = r0 + wr * (BM / 2) + mt * 16 + lr;
            float o0 = cc[mt][nt][0] + b0;
            float o1 = cc[mt][nt][1] + b1;
            float o2 = cc[mt][nt][2] + b0;
            float o3 = cc[mt][nt][3] + b1;
            if (ACT == 1) {
                o0 = 0.5f * o0 * (1.0f + erff(o0 * 0.70710678118654752f));
                o1 = 0.5f * o1 * (1.0f + erff(o1 * 0.70710678118654752f));
                o2 = 0.5f * o2 * (1.0f + erff(o2 * 0.70710678118654752f));
                o3 = 0.5f * o3 * (1.0f + erff(o3 * 0.70710678118654752f));
            }
            *(float2*)&C[(size_t)rlo * N + col]       = make_float2(o0, o1);
            *(float2*)&C[(size_t)(rlo + 8) * N + col] = make_float2(o2, o3);
        }
    }
}

template <int ACT, int BM>
__global__ void __launch_bounds__(256, 2) gemm_mma(const float* __restrict__ A,
                                                   const float* __restrict__ B,
                                                   const float* __restrict__ bias,
                                                   float* __restrict__ C, int N, int K) {
    gemm_core<ACT, BM>(A, B, bias, C, N, K, blockIdx.x * BM, blockIdx.y * 128,
                       (uint32_t*)s_raw);
}

__global__ void __launch_bounds__(256, 2) gemm_qkv(const float* __restrict__ A,
                                                   const float* __restrict__ Bq,
                                                   const float* __restrict__ Bk,
                                                   const float* __restrict__ Bv,
                                                   const float* __restrict__ bq,
                                                   const float* __restrict__ bk,
                                                   const float* __restrict__ bv,
                                                   float* __restrict__ Cq,
                                                   float* __restrict__ Ck,
                                                   float* __restrict__ Cv) {
    const float* B;
    const float* bi;
    float* C;
    if (blockIdx.z == 0)      { B = Bq; bi = bq; C = Cq; }
    else if (blockIdx.z == 1) { B = Bk; bi = bk; C = Ck; }
    else                      { B = Bv; bi = bv; C = Cv; }
    gemm_core<0, 128>(A, B, bi, C, CD, CD, blockIdx.x * 128, blockIdx.y * 128,
                      (uint32_t*)s_raw);
}

// ---------------------------------------------------------------------------
// Tensor-core causal flash attention (tf32 mma.sync), occupancy 1
// ---------------------------------------------------------------------------
__global__ void __launch_bounds__(256, 1) attn_mma(const float* __restrict__ q,
                                                   const float* __restrict__ k,
                                                   const float* __restrict__ v,
                                                   float* __restrict__ o) {
    float* sm = (float*)s_raw;
    constexpr int QW = 68, PWD = 76, KW = 68, VW = 72;
    constexpr int OFF_K = 9728;
    constexpr int KSTG  = 64 * KW;
    constexpr int OFF_V = OFF_K + 2 * KSTG;
    constexpr int VSTG  = 64 * VW;

    const int tid = threadIdx.x, lane = tid & 31, wid = tid >> 5;
    const int g = lane >> 2, t = lane & 3;
    const int qt = (int)(gridDim.x - 1 - blockIdx.x);
    const int h = blockIdx.y, b = blockIdx.z;
    const int qbase = qt * 128;
    const int rowoff = b * CS;
    const int hd = h * CHD;
    const int nkt = 2 * qt + 2;
    const uint32_t smb = (uint32_t)__cvta_generic_to_shared(sm);

#pragma unroll
    for (int it = 0; it < 8; it++) {
        int i = tid + it * 256;
        int r = i >> 4, c = (i & 15) << 2;
        float4 qv = *(const float4*)(q + (size_t)(rowoff + qbase + r) * CD + hd + c);
        qv.x *= 0.125f; qv.y *= 0.125f; qv.z *= 0.125f; qv.w *= 0.125f;
        *(float4*)(sm + r * QW + c) = qv;
    }
#pragma unroll
    for (int j = 0; j < 4; j++) {
        int i = tid + j * 256;
        int r = i >> 4, c = (i & 15) << 2;
        CP_ASYNC16(smb + 4u * (OFF_K + r * KW + c),
                   k + (size_t)(rowoff + r) * CD + hd + c);
        CP_ASYNC16(smb + 4u * (OFF_V + r * VW + c),
                   v + (size_t)(rowoff + r) * CD + hd + c);
    }
    CP_COMMIT();
    __syncthreads();

    uint32_t qf[8][4];
    {
        int r0 = wid * 16 + g;
#pragma unroll
        for (int kk = 0; kk < 8; kk++) {
            qf[kk][0] = f2tf(sm[r0 * QW + kk * 8 + t]);
            qf[kk][1] = f2tf(sm[(r0 + 8) * QW + kk * 8 + t]);
            qf[kk][2] = f2tf(sm[r0 * QW + kk * 8 + t + 4]);
            qf[kk][3] = f2tf(sm[(r0 + 8) * QW + kk * 8 + t + 4]);
        }
    }

    float m0 = -1e30f, m1 = -1e30f, l0 = 0.0f, l1 = 0.0f;
    float o_[8][4];
#pragma unroll
    for (int nt = 0; nt < 8; nt++)
#pragma unroll
        for (int j = 0; j < 4; j++) o_[nt][j] = 0.0f;

    const int wrow = qbase + wid * 16;

#pragma unroll 1
    for (int kt = 0; kt < nkt; kt++) {
        const int s = kt & 1;
        __syncthreads();
        if (kt + 1 < nkt) {
#pragma unroll
            for (int j = 0; j < 4; j++) {
                int i = tid + j * 256;
                int r = i >> 4, c = (i & 15) << 2;
                CP_ASYNC16(smb + 4u * (OFF_K + (s ^ 1) * KSTG + r * KW + c),
                           k + (size_t)(rowoff + (kt + 1) * 64 + r) * CD + hd + c);
                CP_ASYNC16(smb + 4u * (OFF_V + (s ^ 1) * VSTG + r * VW + c),
                           v + (size_t)(rowoff + (kt + 1) * 64 + r) * CD + hd + c);
            }
        }
        CP_COMMIT();
        CP_WAIT1();
        __syncthreads();

        if (kt * 64 > wrow + 15) continue;

        const float* Ks = sm + OFF_K + s * KSTG;
        const float* Vs = sm + OFF_V + s * VSTG;

        float c_[8][4];
#pragma unroll
        for (int nt = 0; nt < 8; nt++)
#pragma unroll
            for (int j = 0; j < 4; j++) c_[nt][j] = 0.0f;
#pragma unroll
        for (int kk = 0; kk < 8; kk++) {
#pragma unroll
            for (int nt = 0; nt < 8; nt++) {
                uint32_t bf[2];
                bf[0] = f2tf(Ks[(nt * 8 + g) * KW + kk * 8 + t]);
                bf[1] = f2tf(Ks[(nt * 8 + g) * KW + kk * 8 + t + 4]);
                mma_tf32(c_[nt], qf[kk], bf);
            }
        }

        if (kt * 64 + 63 > wrow) {
            int r0g = wrow + g, r1g = r0g + 8;
#pragma unroll
            for (int nt = 0; nt < 8; nt++) {
                int col = kt * 64 + nt * 8 + 2 * t;
                if (col     > r0g) c_[nt][0] = -1e9f;
                if (col + 1 > r0g) c_[nt][1] = -1e9f;
                if (col     > r1g) c_[nt][2] = -1e9f;
                if (col + 1 > r1g) c_[nt][3] = -1e9f;
            }
        }

        float tm0 = c_[0][0], tm1 = c_[0][2];
#pragma unroll
        for (int nt = 0; nt < 8; nt++) {
            tm0 = fmaxf(tm0, fmaxf(c_[nt][0], c_[nt][1]));
            tm1 = fmaxf(tm1, fmaxf(c_[nt][2], c_[nt][3]));
        }
        tm0 = fmaxf(tm0, __shfl_xor_sync(0xffffffffu, tm0, 1));
        tm0 = fmaxf(tm0, __shfl_xor_sync(0xffffffffu, tm0, 2));
        tm1 = fmaxf(tm1, __shfl_xor_sync(0xffffffffu, tm1, 1));
        tm1 = fmaxf(tm1, __shfl_xor_sync(0xffffffffu, tm1, 2));

        float mn0 = fmaxf(m0, tm0), mn1 = fmaxf(m1, tm1);
        float al0 = __expf(m0 - mn0), al1 = __expf(m1 - mn1);
        float ls0 = 0.0f, ls1 = 0.0f;
#pragma unroll
        for (int nt = 0; nt < 8; nt++) {
            c_[nt][0] = __expf(c_[nt][0] - mn0);
            c_[nt][1] = __expf(c_[nt][1] - mn0);
            c_[nt][2] = __expf(c_[nt][2] - mn1);
            c_[nt][3] = __expf(c_[nt][3] - mn1);
            ls0 += c_[nt][0] + c_[nt][1];
            ls1 += c_[nt][2] + c_[nt][3];
        }
        ls0 += __shfl_xor_sync(0xffffffffu, ls0, 1);
        ls0 += __shfl_xor_sync(0xffffffffu, ls0, 2);
        ls1 += __shfl_xor_sync(0xffffffffu, ls1, 1);
        ls1 += __shfl_xor_sync(0xffffffffu, ls1, 2);
        l0 = l0 * al0 + ls0; m0 = mn0;
        l1 = l1 * al1 + ls1; m1 = mn1;
#pragma unroll
        for (int nt = 0; nt < 8; nt++) {
            o_[nt][0] *= al0; o_[nt][1] *= al0;
            o_[nt][2] *= al1; o_[nt][3] *= al1;
        }

        float* Pw = sm + wid * 16 * PWD;
#pragma unroll
        for (int nt = 0; nt < 8; nt++) {
            int cc0 = nt * 8 + 2 * t;
            Pw[g * PWD + cc0]           = __uint_as_float(f2tf(c_[nt][0]));
            Pw[g * PWD + cc0 + 1]       = __uint_as_float(f2tf(c_[nt][1]));
            Pw[(g + 8) * PWD + cc0]     = __uint_as_float(f2tf(c_[nt][2]));
            Pw[(g + 8) * PWD + cc0 + 1] = __uint_as_float(f2tf(c_[nt][3]));
        }
        __syncwarp();

#pragma unroll
        for (int kk = 0; kk < 8; kk++) {
            uint32_t af[4];
            af[0] = __float_as_uint(Pw[g * PWD + kk * 8 + t]);
            af[1] = __float_as_uint(Pw[(g + 8) * PWD + kk * 8 + t]);
            af[2] = __float_as_uint(Pw[g * PWD + kk * 8 + t + 4]);
            af[3] = __float_as_uint(Pw[(g + 8) * PWD + kk * 8 + t + 4]);
#pragma unroll
            for (int nt = 0; nt < 8; nt++) {
                uint32_t bf[2];
                bf[0] = f2tf(Vs[(kk * 8 + t) * VW + nt * 8 + g]);
                bf[1] = f2tf(Vs[(kk * 8 + t + 4) * VW + nt * 8 + g]);
                mma_tf32(o_[nt], af, bf);
            }
        }
        __syncwarp();
    }

    float i0 = 1.0f / l0, i1 = 1.0f / l1;
    int row0 = rowoff + qbase + wid * 16 + g;
#pragma unroll
    for (int nt = 0; nt < 8; nt++) {
        int col = hd + nt * 8 + 2 * t;
        *(float2*)&o[(size_t)row0 * CD + col] = make_float2(o_[nt][0] * i0, o_[nt][1] * i0);
        *(float2*)&o[(size_t)(row0 + 8) * CD + col] = make_float2(o_[nt][2] * i1, o_[nt][3] * i1);
    }
}

// ---------------------------------------------------------------------------
// LayerNorm
// ---------------------------------------------------------------------------
__global__ void ln_kernel(const float* __restrict__ x, const float* __restrict__ res,
                          const float* __restrict__ g, const float* __restrict__ b,
                          float* __restrict__ out) {
    int r = blockIdx.x, t = threadIdx.x;
    __shared__ float red[8];
    int base = r * CD;
    float a0 = x[base + t], a1 = x[base + t + 256], a2 = x[base + t + 512];
    if (res) {
        a0 += res[base + t];
        a1 += res[base + t + 256];
        a2 += res[base + t + 512];
    }
    float sm = a0 + a1 + a2;
#pragma unroll
    for (int o = 16; o; o >>= 1) sm += __shfl_xor_sync(0xffffffffu, sm, o);
    if ((t & 31) == 0) red[t >> 5] = sm;
    __syncthreads();
    float mean = (red[0] + red[1] + red[2] + red[3] + red[4] + red[5] + red[6] + red[7]) *
                 (1.0f / CD);
    __syncthreads();
    float d0 = a0 - mean, d1 = a1 - mean, d2 = a2 - mean;
    float vs = d0 * d0 + d1 * d1 + d2 * d2;
#pragma unroll
    for (int o = 16; o; o >>= 1) vs += __shfl_xor_sync(0xffffffffu, vs, o);
    if ((t & 31) == 0) red[t >> 5] = vs;
    __syncthreads();
    float var = (red[0] + red[1] + red[2] + red[3] + red[4] + red[5] + red[6] + red[7]) *
                (1.0f / CD);
    float rstd = rsqrtf(var + 1e-5f);
    out[base + t]       = d0 * rstd * g[t]       + b[t];
    out[base + t + 256] = d1 * rstd * g[t + 256] + b[t + 256];
    out[base + t + 512] = d2 * rstd * g[t + 512] + b[t + 512];
}

// ---------------------------------------------------------------------------
// Launch
// ---------------------------------------------------------------------------
extern "C" void kernel_launch(void* const* d_in, const int* in_sizes, int n_in,
                              void* d_out, int out_size) {
    const int*   ids   = (const int*)  d_in[0];
    const float* emb   = (const float*)d_in[1];
    const float* pe    = (const float*)d_in[2];
    const float* wq    = (const float*)d_in[3];
    const float* bq    = (const float*)d_in[4];
    const float* wk    = (const float*)d_in[5];
    const float* bk    = (const float*)d_in[6];
    const float* wv    = (const float*)d_in[7];
    const float* bv    = (const float*)d_in[8];
    const float* wo    = (const float*)d_in[9];
    const float* bo    = (const float*)d_in[10];
    const float* ln1g  = (const float*)d_in[11];
    const float* ln1b  = (const float*)d_in[12];
    const float* w1    = (const float*)d_in[13];
    const float* b1    = (const float*)d_in[14];
    const float* w2    = (const float*)d_in[15];
    const float* b2    = (const float*)d_in[16];
    const float* ln2g  = (const float*)d_in[17];
    const float* ln2b  = (const float*)d_in[18];
    const float* lnfg  = (const float*)d_in[19];
    const float* lnfb  = (const float*)d_in[20];
    const float* headw = (const float*)d_in[21];
    const float* headb = (const float*)d_in[22];
    float* out = (float*)d_out;

    float *x, *q, *k, *v, *att, *ff;
    cudaGetSymbolAddress((void**)&x,   g_x);
    cudaGetSymbolAddress((void**)&q,   g_q);
    cudaGetSymbolAddress((void**)&k,   g_k);
    cudaGetSymbolAddress((void**)&v,   g_v);
    cudaGetSymbolAddress((void**)&att, g_att);
    cudaGetSymbolAddress((void**)&ff,  g_ff);

    const int SMEM_ATTN  = (9728 + 2 * 4352 + 2 * 4608) * 4;      // 110592
    const int SMEM_G128  = (2 * 128 * 36 + 2 * 32 * 128) * 4;     // 69632
    const int SMEM_G64   = (2 * 64 * 36 + 2 * 32 * 128) * 4;      // 51200
    cudaFuncSetAttribute(attn_mma, cudaFuncAttributeMaxDynamicSharedMemorySize, SMEM_ATTN);
    cudaFuncSetAttribute(gemm_mma<0, 128>, cudaFuncAttributeMaxDynamicSharedMemorySize, SMEM_G128);
    cudaFuncSetAttribute(gemm_mma<1, 128>, cudaFuncAttributeMaxDynamicSharedMemorySize, SMEM_G128);
    cudaFuncSetAttribute(gemm_mma<0, 64>,  cudaFuncAttributeMaxDynamicSharedMemorySize, SMEM_G64);
    cudaFuncSetAttribute(gemm_qkv, cudaFuncAttributeMaxDynamicSharedMemorySize, SMEM_G128);

    embed_kernel<<<(CM * CD + 255) / 256, 256>>>(ids, emb, pe, x);

    dim3 gQKV(CM / 128, CD / 128, 3);   // 288
    dim3 gP64(CM / 64,  CD / 128);      // 192
    dim3 gF1 (CM / 128, CF / 128);      // 384
    dim3 gH  (CM / 128, CV / 128);      // 4000
    dim3 gATT(CS / 128, CH, CB);        // 192

    for (int l = 0; l < CL; l++) {
        size_t wOff = (size_t)l * CD * CD;
        gemm_qkv<<<gQKV, 256, SMEM_G128>>>(x, wq + wOff, wk + wOff, wv + wOff,
                                           bq + l * CD, bk + l * CD, bv + l * CD, q, k, v);
        attn_mma<<<gATT, 256, SMEM_ATTN>>>(q, k, v, att);
        gemm_mma<0, 64><<<gP64, 256, SMEM_G64>>>(att, wo + wOff, bo + l * CD, q, CD, CD);
        ln_kernel<<<CM, 256>>>(x, q, ln1g + l * CD, ln1b + l * CD, x);
        gemm_mma<1, 128><<<gF1, 256, SMEM_G128>>>(x, w1 + (size_t)l * CD * CF,
                                                  b1 + l * CF, ff, CF, CD);
        gemm_mma<0, 64><<<gP64, 256, SMEM_G64>>>(ff, w2 + (size_t)l * CF * CD,
                                                 b2 + l * CD, q, CD, CF);
        ln_kernel<<<CM, 256>>>(x, q, ln2g + l * CD, ln2b + l * CD, x);
    }

    ln_kernel<<<CM, 256>>>(x, nullptr, lnfg, lnfb, q);
    gemm_mma<0, 128><<<gH, 256, SMEM_G128>>>(q, headw, headb, out, CV, CD);
}

// round 17
// speedup vs baseline: 1.9112x; 1.0198x over previous
#include <cuda_runtime.h>
#include <math.h>
#include <stdint.h>

// Model constants
constexpr int CD  = 768;
constexpr int CS  = 1024;
constexpr int CB  = 2;
constexpr int CM  = CB * CS;  // 2048
constexpr int CH  = 12;
constexpr int CHD = 64;
constexpr int CL  = 6;
constexpr int CF  = 3072;
constexpr int CV  = 32000;

// Scratch
__device__ float g_x  [CM * CD];
__device__ float g_q  [CM * CD];
__device__ float g_k  [CM * CD];
__device__ float g_v  [CM * CD];
__device__ float g_att[CM * CD];
__device__ float g_ff [CM * CF];

// Single extern shared symbol, cast per-kernel
extern __shared__ char s_raw[];

// ---------------------------------------------------------------------------
// Helpers
// ---------------------------------------------------------------------------
__device__ __forceinline__ uint32_t f2tf(float f) {
    uint32_t u;
    asm("cvt.rna.tf32.f32 %0, %1;" : "=r"(u) : "f"(f));
    return u;
}
__device__ __forceinline__ void mma_tf32(float* c, const uint32_t* a, const uint32_t* b) {
    asm volatile(
        "mma.sync.aligned.m16n8k8.row.col.f32.tf32.tf32.f32 "
        "{%0,%1,%2,%3}, {%4,%5,%6,%7}, {%8,%9}, {%0,%1,%2,%3};"
        : "+f"(c[0]), "+f"(c[1]), "+f"(c[2]), "+f"(c[3])
        : "r"(a[0]), "r"(a[1]), "r"(a[2]), "r"(a[3]), "r"(b[0]), "r"(b[1]));
}
#define CP_ASYNC16(dst, src) \
    asm volatile("cp.async.ca.shared.global [%0], [%1], 16;" :: "r"(dst), "l"(src))
#define CP_COMMIT() asm volatile("cp.async.commit_group;")
#define CP_WAIT0()  asm volatile("cp.async.wait_group 0;")
#define CP_WAIT1()  asm volatile("cp.async.wait_group 1;")

// ---------------------------------------------------------------------------
// Embedding
// ---------------------------------------------------------------------------
__global__ void embed_kernel(const int* __restrict__ ids, const float* __restrict__ emb,
                             const float* __restrict__ pe, float* __restrict__ out) {
    int idx = blockIdx.x * blockDim.x + threadIdx.x;
    if (idx >= CM * CD) return;
    int r = idx / CD;
    int d = idx - r * CD;
    int s = r & (CS - 1);
    out[idx] = emb[ids[r] * CD + d] * 27.712812921102035f + pe[s * CD + d];
}

// ---------------------------------------------------------------------------
// tf32 mma.sync GEMM core (R15 + ldmatrix A-fragment loads):
// C = A @ B + bias (ACT=1: GELU). BM x 128 CTA tile, BK=32, 2-stage pipeline.
// A fragments via ldmatrix.m8n8.x4.b16 (1 instr per m16k8 tile; tf32 row of
// 4 values = 16B = one b16 8x8 tile row). B raw fp32 via cp.async with tf32
// cvt at fragment load. A: LDG->cvt->STS, [m][36]. B: [k][n ^ ((k&3)<<3)].
// ---------------------------------------------------------------------------
template <int ACT, int BM>
__device__ __forceinline__ void gemm_core(const float* __restrict__ A,
                                          const float* __restrict__ B,
                                          const float* __restrict__ bias,
                                          float* __restrict__ C,
                                          int N, int K, int r0, int c0,
                                          uint32_t* sm) {
    constexpr int AW  = 36;          // 32 k-words + 4 pad
    constexpr int SA  = BM * AW;     // A stage words
    constexpr int SB  = 32 * 128;    // B stage words (4096)
    constexpr int ABo = 2 * SA;      // B region word offset
    constexpr int AIT = BM / 32;     // A float4 per thread per stage
    constexpr int MT  = BM / 32;     // 16-row m-tiles per warp

    const int tid  = threadIdx.x;
    const int lane = tid & 31;
    const int wid  = tid >> 5;
    const int wr   = wid >> 2;
    const int wc   = wid & 3;
    const int lr   = lane >> 2;
    const int lc   = lane & 3;
    const int NK   = K >> 5;

    const float* Ag = A + (size_t)r0 * K;
    const float* Bg = B + c0;
    const uint32_t smb = (uint32_t)__cvta_generic_to_shared(sm);

    float cc[MT][4][4];
#pragma unroll
    for (int mt = 0; mt < MT; mt++)
#pragma unroll
        for (int nt = 0; nt < 4; nt++)
#pragma unroll
            for (int j = 0; j < 4; j++) cc[mt][nt][j] = 0.0f;

    // A staging coords: idx = tid + it*256 -> row = idx>>3, k4 = (idx&7)*4
    int am[AIT], ak[AIT];
#pragma unroll
    for (int it = 0; it < AIT; it++) {
        int i = tid + it * 256;
        am[it] = i >> 3;
        ak[it] = (i & 7) << 2;
    }
    // B staging coords: idx = tid + it*256 (it<4) -> k = idx>>5, n4 = (idx&31)*4
    int bk[4], bn[4];
#pragma unroll
    for (int it = 0; it < 4; it++) {
        int i = tid + it * 256;
        bk[it] = i >> 5;
        bn[it] = (i & 31) << 2;
    }

    float4 rA[AIT];

    // ---- prologue: chunk 0 ----
#pragma unroll
    for (int it = 0; it < AIT; it++)
        rA[it] = *(const float4*)(Ag + (size_t)am[it] * K + ak[it]);
#pragma unroll
    for (int it = 0; it < 4; it++) {
        uint32_t dst = smb + 4u * (ABo + bk[it] * 128 + (bn[it] ^ ((bk[it] & 3) << 3)));
        CP_ASYNC16(dst, Bg + (size_t)bk[it] * N + bn[it]);
    }
    CP_COMMIT();
#pragma unroll
    for (int it = 0; it < AIT; it++) {
        uint4 v;
        v.x = f2tf(rA[it].x);
        v.y = f2tf(rA[it].y);
        v.z = f2tf(rA[it].z);
        v.w = f2tf(rA[it].w);
        *(uint4*)&sm[am[it] * AW + ak[it]] = v;
    }
    // LDG A chunk 1
    if (NK > 1) {
#pragma unroll
        for (int it = 0; it < AIT; it++)
            rA[it] = *(const float4*)(Ag + (size_t)am[it] * K + 32 + ak[it]);
    }

    const int xb = lc << 3;  // B swizzle term: (k0&3)<<3 == lc<<3 for k0 = ks*8+lc
    // ldmatrix per-lane row/col terms (invariant over loop):
    //   row = wr*(BM/2) + mt*16 + (lane & 15); col-offset = (lane>>4)*4
    const int lmrow = wr * (BM / 2) + (lane & 15);
    const int lmcol = (lane >> 4) << 2;

    // ---- main loop ----
#pragma unroll 1
    for (int j = 0; j < NK; j++) {
        const int s = j & 1;
        CP_WAIT0();
        __syncthreads();

        if (j + 1 < NK) {
            const int s1 = s ^ 1;
            // B(j+1) -> stage s1
#pragma unroll
            for (int it = 0; it < 4; it++) {
                uint32_t dst = smb + 4u * (ABo + s1 * SB + bk[it] * 128 +
                                           (bn[it] ^ ((bk[it] & 3) << 3)));
                CP_ASYNC16(dst, Bg + (size_t)((j + 1) * 32 + bk[it]) * N + bn[it]);
            }
            // A(j+1): STS from rA
            uint32_t* As1 = sm + s1 * SA;
#pragma unroll
            for (int it = 0; it < AIT; it++) {
                uint4 v;
                v.x = f2tf(rA[it].x);
                v.y = f2tf(rA[it].y);
                v.z = f2tf(rA[it].z);
                v.w = f2tf(rA[it].w);
                *(uint4*)&As1[am[it] * AW + ak[it]] = v;
            }
            // LDG A(j+2)
            if (j + 2 < NK) {
#pragma unroll
                for (int it = 0; it < AIT; it++)
                    rA[it] = *(const float4*)(Ag + (size_t)am[it] * K + (j + 2) * 32 + ak[it]);
            }
        }
        CP_COMMIT();

        const uint32_t* Bs_ = sm + ABo + s * SB;
        const uint32_t aBase = smb + 4u * (s * SA + lmrow * AW + lmcol);

        // B-fragment prefetch pipeline over 4 k-slices
        uint32_t bf[2][4][2];
        {
            const int k0 = lc;
#pragma unroll
            for (int nt = 0; nt < 4; nt++) {
                int n = wc * 32 + nt * 8 + lr;
                bf[0][nt][0] = f2tf(__uint_as_float(Bs_[k0 * 128 + (n ^ xb)]));
                bf[0][nt][1] = f2tf(__uint_as_float(Bs_[(k0 + 4) * 128 + (n ^ xb)]));
            }
        }
#pragma unroll
        for (int ks = 0; ks < 4; ks++) {
            if (ks < 3) {
                const int k0 = (ks + 1) * 8 + lc;
#pragma unroll
                for (int nt = 0; nt < 4; nt++) {
                    int n = wc * 32 + nt * 8 + lr;
                    bf[(ks + 1) & 1][nt][0] = f2tf(__uint_as_float(Bs_[k0 * 128 + (n ^ xb)]));
                    bf[(ks + 1) & 1][nt][1] = f2tf(__uint_as_float(Bs_[(k0 + 4) * 128 + (n ^ xb)]));
                }
            }
            uint32_t af[MT][4];
#pragma unroll
            for (int mt = 0; mt < MT; mt++) {
                uint32_t a_addr = aBase + 4u * (mt * 16 * AW + ks * 8);
                asm volatile(
                    "ldmatrix.sync.aligned.m8n8.x4.shared.b16 {%0,%1,%2,%3}, [%4];"
                    : "=r"(af[mt][0]), "=r"(af[mt][1]), "=r"(af[mt][2]), "=r"(af[mt][3])
                    : "r"(a_addr));
            }
#pragma unroll
            for (int mt = 0; mt < MT; mt++)
#pragma unroll
                for (int nt = 0; nt < 4; nt++) mma_tf32(cc[mt][nt], af[mt], bf[ks & 1][nt]);
        }
    }

    // ---- epilogue ----
#pragma unroll
    for (int nt = 0; nt < 4; nt++) {
        int col = c0 + wc * 32 + nt * 8 + 2 * lc;
        float b0 = bias[col], b1 = bias[col + 1];
#pragma unroll
        for (int mt = 0; mt < MT; mt++) {
            int rlo = r0 + wr * (BM / 2) + mt * 16 + lr;
            float o0 = cc[mt][nt][0] + b0;
            float o1 = cc[mt][nt][1] + b1;
            float o2 = cc[mt][nt][2] + b0;
            float o3 = cc[mt][nt][3] + b1;
            if (ACT == 1) {
                o0 = 0.5f * o0 * (1.0f + erff(o0 * 0.70710678118654752f));
                o1 = 0.5f * o1 * (1.0f + erff(o1 * 0.70710678118654752f));
                o2 = 0.5f * o2 * (1.0f + erff(o2 * 0.70710678118654752f));
                o3 = 0.5f * o3 * (1.0f + erff(o3 * 0.70710678118654752f));
            }
            *(float2*)&C[(size_t)rlo * N + col]       = make_float2(o0, o1);
            *(float2*)&C[(size_t)(rlo + 8) * N + col] = make_float2(o2, o3);
        }
    }
}

template <int ACT, int BM>
__global__ void __launch_bounds__(256, 2) gemm_mma(const float* __restrict__ A,
                                                   const float* __restrict__ B,
                                                   const float* __restrict__ bias,
                                                   float* __restrict__ C, int N, int K) {
    gemm_core<ACT, BM>(A, B, bias, C, N, K, blockIdx.x * BM, blockIdx.y * 128,
                       (uint32_t*)s_raw);
}

__global__ void __launch_bounds__(256, 2) gemm_qkv(const float* __restrict__ A,
                                                   const float* __restrict__ Bq,
                                                   const float* __restrict__ Bk,
                                                   const float* __restrict__ Bv,
                                                   const float* __restrict__ bq,
                                                   const float* __restrict__ bk,
                                                   const float* __restrict__ bv,
                                                   float* __restrict__ Cq,
                                                   float* __restrict__ Ck,
                                                   float* __restrict__ Cv) {
    const float* B;
    const float* bi;
    float* C;
    if (blockIdx.z == 0)      { B = Bq; bi = bq; C = Cq; }
    else if (blockIdx.z == 1) { B = Bk; bi = bk; C = Ck; }
    else                      { B = Bv; bi = bv; C = Cv; }
    gemm_core<0, 128>(A, B, bi, C, CD, CD, blockIdx.x * 128, blockIdx.y * 128,
                      (uint32_t*)s_raw);
}

// ---------------------------------------------------------------------------
// Tensor-core causal flash attention (tf32 mma.sync), occupancy 1 — unchanged
// ---------------------------------------------------------------------------
__global__ void __launch_bounds__(256, 1) attn_mma(const float* __restrict__ q,
                                                   const float* __restrict__ k,
                                                   const float* __restrict__ v,
                                                   float* __restrict__ o) {
    float* sm = (float*)s_raw;
    constexpr int QW = 68, PWD = 76, KW = 68, VW = 72;
    constexpr int OFF_K = 9728;
    constexpr int KSTG  = 64 * KW;
    constexpr int OFF_V = OFF_K + 2 * KSTG;
    constexpr int VSTG  = 64 * VW;

    const int tid = threadIdx.x, lane = tid & 31, wid = tid >> 5;
    const int g = lane >> 2, t = lane & 3;
    const int qt = (int)(gridDim.x - 1 - blockIdx.x);
    const int h = blockIdx.y, b = blockIdx.z;
    const int qbase = qt * 128;
    const int rowoff = b * CS;
    const int hd = h * CHD;
    const int nkt = 2 * qt + 2;
    const uint32_t smb = (uint32_t)__cvta_generic_to_shared(sm);

#pragma unroll
    for (int it = 0; it < 8; it++) {
        int i = tid + it * 256;
        int r = i >> 4, c = (i & 15) << 2;
        float4 qv = *(const float4*)(q + (size_t)(rowoff + qbase + r) * CD + hd + c);
        qv.x *= 0.125f; qv.y *= 0.125f; qv.z *= 0.125f; qv.w *= 0.125f;
        *(float4*)(sm + r * QW + c) = qv;
    }
#pragma unroll
    for (int j = 0; j < 4; j++) {
        int i = tid + j * 256;
        int r = i >> 4, c = (i & 15) << 2;
        CP_ASYNC16(smb + 4u * (OFF_K + r * KW + c),
                   k + (size_t)(rowoff + r) * CD + hd + c);
        CP_ASYNC16(smb + 4u * (OFF_V + r * VW + c),
                   v + (size_t)(rowoff + r) * CD + hd + c);
    }
    CP_COMMIT();
    __syncthreads();

    uint32_t qf[8][4];
    {
        int r0 = wid * 16 + g;
#pragma unroll
        for (int kk = 0; kk < 8; kk++) {
            qf[kk][0] = f2tf(sm[r0 * QW + kk * 8 + t]);
            qf[kk][1] = f2tf(sm[(r0 + 8) * QW + kk * 8 + t]);
            qf[kk][2] = f2tf(sm[r0 * QW + kk * 8 + t + 4]);
            qf[kk][3] = f2tf(sm[(r0 + 8) * QW + kk * 8 + t + 4]);
        }
    }

    float m0 = -1e30f, m1 = -1e30f, l0 = 0.0f, l1 = 0.0f;
    float o_[8][4];
#pragma unroll
    for (int nt = 0; nt < 8; nt++)
#pragma unroll
        for (int j = 0; j < 4; j++) o_[nt][j] = 0.0f;

    const int wrow = qbase + wid * 16;

#pragma unroll 1
    for (int kt = 0; kt < nkt; kt++) {
        const int s = kt & 1;
        __syncthreads();
        if (kt + 1 < nkt) {
#pragma unroll
            for (int j = 0; j < 4; j++) {
                int i = tid + j * 256;
                int r = i >> 4, c = (i & 15) << 2;
                CP_ASYNC16(smb + 4u * (OFF_K + (s ^ 1) * KSTG + r * KW + c),
                           k + (size_t)(rowoff + (kt + 1) * 64 + r) * CD + hd + c);
                CP_ASYNC16(smb + 4u * (OFF_V + (s ^ 1) * VSTG + r * VW + c),
                           v + (size_t)(rowoff + (kt + 1) * 64 + r) * CD + hd + c);
            }
        }
        CP_COMMIT();
        CP_WAIT1();
        __syncthreads();

        if (kt * 64 > wrow + 15) continue;

        const float* Ks = sm + OFF_K + s * KSTG;
        const float* Vs = sm + OFF_V + s * VSTG;

        float c_[8][4];
#pragma unroll
        for (int nt = 0; nt < 8; nt++)
#pragma unroll
            for (int j = 0; j < 4; j++) c_[nt][j] = 0.0f;
#pragma unroll
        for (int kk = 0; kk < 8; kk++) {
#pragma unroll
            for (int nt = 0; nt < 8; nt++) {
                uint32_t bf[2];
                bf[0] = f2tf(Ks[(nt * 8 + g) * KW + kk * 8 + t]);
                bf[1] = f2tf(Ks[(nt * 8 + g) * KW + kk * 8 + t + 4]);
                mma_tf32(c_[nt], qf[kk], bf);
            }
        }

        if (kt * 64 + 63 > wrow) {
            int r0g = wrow + g, r1g = r0g + 8;
#pragma unroll
            for (int nt = 0; nt < 8; nt++) {
                int col = kt * 64 + nt * 8 + 2 * t;
                if (col     > r0g) c_[nt][0] = -1e9f;
                if (col + 1 > r0g) c_[nt][1] = -1e9f;
                if (col     > r1g) c_[nt][2] = -1e9f;
                if (col + 1 > r1g) c_[nt][3] = -1e9f;
            }
        }

        float tm0 = c_[0][0], tm1 = c_[0][2];
#pragma unroll
        for (int nt = 0; nt < 8; nt++) {
            tm0 = fmaxf(tm0, fmaxf(c_[nt][0], c_[nt][1]));
            tm1 = fmaxf(tm1, fmaxf(c_[nt][2], c_[nt][3]));
        }
        tm0 = fmaxf(tm0, __shfl_xor_sync(0xffffffffu, tm0, 1));
        tm0 = fmaxf(tm0, __shfl_xor_sync(0xffffffffu, tm0, 2));
        tm1 = fmaxf(tm1, __shfl_xor_sync(0xffffffffu, tm1, 1));
        tm1 = fmaxf(tm1, __shfl_xor_sync(0xffffffffu, tm1, 2));

        float mn0 = fmaxf(m0, tm0), mn1 = fmaxf(m1, tm1);
        float al0 = __expf(m0 - mn0), al1 = __expf(m1 - mn1);
        float ls0 = 0.0f, ls1 = 0.0f;
#pragma unroll
        for (int nt = 0; nt < 8; nt++) {
            c_[nt][0] = __expf(c_[nt][0] - mn0);
            c_[nt][1] = __expf(c_[nt][1] - mn0);
            c_[nt][2] = __expf(c_[nt][2] - mn1);
            c_[nt][3] = __expf(c_[nt][3] - mn1);
            ls0 += c_[nt][0] + c_[nt][1];
            ls1 += c_[nt][2] + c_[nt][3];
        }
        ls0 += __shfl_xor_sync(0xffffffffu, ls0, 1);
        ls0 += __shfl_xor_sync(0xffffffffu, ls0, 2);
        ls1 += __shfl_xor_sync(0xffffffffu, ls1, 1);
        ls1 += __shfl_xor_sync(0xffffffffu, ls1, 2);
        l0 = l0 * al0 + ls0; m0 = mn0;
        l1 = l1 * al1 + ls1; m1 = mn1;
#pragma unroll
        for (int nt = 0; nt < 8; nt++) {
            o_[nt][0] *= al0; o_[nt][1] *= al0;
            o_[nt][2] *= al1; o_[nt][3] *= al1;
        }

        float* Pw = sm + wid * 16 * PWD;
#pragma unroll
        for (int nt = 0; nt < 8; nt++) {
            int cc0 = nt * 8 + 2 * t;
            Pw[g * PWD + cc0]           = __uint_as_float(f2tf(c_[nt][0]));
            Pw[g * PWD + cc0 + 1]       = __uint_as_float(f2tf(c_[nt][1]));
            Pw[(g + 8) * PWD + cc0]     = __uint_as_float(f2tf(c_[nt][2]));
            Pw[(g + 8) * PWD + cc0 + 1] = __uint_as_float(f2tf(c_[nt][3]));
        }
        __syncwarp();

#pragma unroll
        for (int kk = 0; kk < 8; kk++) {
            uint32_t af[4];
            af[0] = __float_as_uint(Pw[g * PWD + kk * 8 + t]);
            af[1] = __float_as_uint(Pw[(g + 8) * PWD + kk * 8 + t]);
            af[2] = __float_as_uint(Pw[g * PWD + kk * 8 + t + 4]);
            af[3] = __float_as_uint(Pw[(g + 8) * PWD + kk * 8 + t + 4]);
#pragma unroll
            for (int nt = 0; nt < 8; nt++) {
                uint32_t bf[2];
                bf[0] = f2tf(Vs[(kk * 8 + t) * VW + nt * 8 + g]);
                bf[1] = f2tf(Vs[(kk * 8 + t + 4) * VW + nt * 8 + g]);
                mma_tf32(o_[nt], af, bf);
            }
        }
        __syncwarp();
    }

    float i0 = 1.0f / l0, i1 = 1.0f / l1;
    int row0 = rowoff + qbase + wid * 16 + g;
#pragma unroll
    for (int nt = 0; nt < 8; nt++) {
        int col = hd + nt * 8 + 2 * t;
        *(float2*)&o[(size_t)row0 * CD + col] = make_float2(o_[nt][0] * i0, o_[nt][1] * i0);
        *(float2*)&o[(size_t)(row0 + 8) * CD + col] = make_float2(o_[nt][2] * i1, o_[nt][3] * i1);
    }
}

// ---------------------------------------------------------------------------
// LayerNorm
// ---------------------------------------------------------------------------
__global__ void ln_kernel(const float* __restrict__ x, const float* __restrict__ res,
                          const float* __restrict__ g, const float* __restrict__ b,
                          float* __restrict__ out) {
    int r = blockIdx.x, t = threadIdx.x;
    __shared__ float red[8];
    int base = r * CD;
    float a0 = x[base + t], a1 = x[base + t + 256], a2 = x[base + t + 512];
    if (res) {
        a0 += res[base + t];
        a1 += res[base + t + 256];
        a2 += res[base + t + 512];
    }
    float sm = a0 + a1 + a2;
#pragma unroll
    for (int o = 16; o; o >>= 1) sm += __shfl_xor_sync(0xffffffffu, sm, o);
    if ((t & 31) == 0) red[t >> 5] = sm;
    __syncthreads();
    float mean = (red[0] + red[1] + red[2] + red[3] + red[4] + red[5] + red[6] + red[7]) *
                 (1.0f / CD);
    __syncthreads();
    float d0 = a0 - mean, d1 = a1 - mean, d2 = a2 - mean;
    float vs = d0 * d0 + d1 * d1 + d2 * d2;
#pragma unroll
    for (int o = 16; o; o >>= 1) vs += __shfl_xor_sync(0xffffffffu, vs, o);
    if ((t & 31) == 0) red[t >> 5] = vs;
    __syncthreads();
    float var = (red[0] + red[1] + red[2] + red[3] + red[4] + red[5] + red[6] + red[7]) *
                (1.0f / CD);
    float rstd = rsqrtf(var + 1e-5f);
    out[base + t]       = d0 * rstd * g[t]       + b[t];
    out[base + t + 256] = d1 * rstd * g[t + 256] + b[t + 256];
    out[base + t + 512] = d2 * rstd * g[t + 512] + b[t + 512];
}

// ---------------------------------------------------------------------------
// Launch
// ---------------------------------------------------------------------------
extern "C" void kernel_launch(void* const* d_in, const int* in_sizes, int n_in,
                              void* d_out, int out_size) {
    const int*   ids   = (const int*)  d_in[0];
    const float* emb   = (const float*)d_in[1];
    const float* pe    = (const float*)d_in[2];
    const float* wq    = (const float*)d_in[3];
    const float* bq    = (const float*)d_in[4];
    const float* wk    = (const float*)d_in[5];
    const float* bk    = (const float*)d_in[6];
    const float* wv    = (const float*)d_in[7];
    const float* bv    = (const float*)d_in[8];
    const float* wo    = (const float*)d_in[9];
    const float* bo    = (const float*)d_in[10];
    const float* ln1g  = (const float*)d_in[11];
    const float* ln1b  = (const float*)d_in[12];
    const float* w1    = (const float*)d_in[13];
    const float* b1    = (const float*)d_in[14];
    const float* w2    = (const float*)d_in[15];
    const float* b2    = (const float*)d_in[16];
    const float* ln2g  = (const float*)d_in[17];
    const float* ln2b  = (const float*)d_in[18];
    const float* lnfg  = (const float*)d_in[19];
    const float* lnfb  = (const float*)d_in[20];
    const float* headw = (const float*)d_in[21];
    const float* headb = (const float*)d_in[22];
    float* out = (float*)d_out;

    float *x, *q, *k, *v, *att, *ff;
    cudaGetSymbolAddress((void**)&x,   g_x);
    cudaGetSymbolAddress((void**)&q,   g_q);
    cudaGetSymbolAddress((void**)&k,   g_k);
    cudaGetSymbolAddress((void**)&v,   g_v);
    cudaGetSymbolAddress((void**)&att, g_att);
    cudaGetSymbolAddress((void**)&ff,  g_ff);

    const int SMEM_ATTN  = (9728 + 2 * 4352 + 2 * 4608) * 4;      // 110592
    const int SMEM_G128  = (2 * 128 * 36 + 2 * 32 * 128) * 4;     // 69632
    const int SMEM_G64   = (2 * 64 * 36 + 2 * 32 * 128) * 4;      // 51200
    cudaFuncSetAttribute(attn_mma, cudaFuncAttributeMaxDynamicSharedMemorySize, SMEM_ATTN);
    cudaFuncSetAttribute(gemm_mma<0, 128>, cudaFuncAttributeMaxDynamicSharedMemorySize, SMEM_G128);
    cudaFuncSetAttribute(gemm_mma<1, 128>, cudaFuncAttributeMaxDynamicSharedMemorySize, SMEM_G128);
    cudaFuncSetAttribute(gemm_mma<0, 64>,  cudaFuncAttributeMaxDynamicSharedMemorySize, SMEM_G64);
    cudaFuncSetAttribute(gemm_qkv, cudaFuncAttributeMaxDynamicSharedMemorySize, SMEM_G128);

    embed_kernel<<<(CM * CD + 255) / 256, 256>>>(ids, emb, pe, x);

    dim3 gQKV(CM / 128, CD / 128, 3);   // 288
    dim3 gP64(CM / 64,  CD / 128);      // 192
    dim3 gF1 (CM / 128, CF / 128);      // 384
    dim3 gH  (CM / 128, CV / 128);      // 4000
    dim3 gATT(CS / 128, CH, CB);        // 192

    for (int l = 0; l < CL; l++) {
        size_t wOff = (size_t)l * CD * CD;
        gemm_qkv<<<gQKV, 256, SMEM_G128>>>(x, wq + wOff, wk + wOff, wv + wOff,
                                           bq + l * CD, bk + l * CD, bv + l * CD, q, k, v);
        attn_mma<<<gATT, 256, SMEM_ATTN>>>(q, k, v, att);
        gemm_mma<0, 64><<<gP64, 256, SMEM_G64>>>(att, wo + wOff, bo + l * CD, q, CD, CD);
        ln_kernel<<<CM, 256>>>(x, q, ln1g + l * CD, ln1b + l * CD, x);
        gemm_mma<1, 128><<<gF1, 256, SMEM_G128>>>(x, w1 + (size_t)l * CD * CF,
                                                  b1 + l * CF, ff, CF, CD);
        gemm_mma<0, 64><<<gP64, 256, SMEM_G64>>>(ff, w2 + (size_t)l * CF * CD,
                                                 b2 + l * CD, q, CD, CF);
        ln_kernel<<<CM, 256>>>(x, q, ln2g + l * CD, ln2b + l * CD, x);
    }

    ln_kernel<<<CM, 256>>>(x, nullptr, lnfg, lnfb, q);
    gemm_mma<0, 128><<<gH, 256, SMEM_G128>>>(q, headw, headb, out, CV, CD);
}